// round 1
// baseline (speedup 1.0000x reference)
#include <cuda_runtime.h>
#include <math.h>

#define NB 4
#define NS 2048
#define ND 1024
#define NH 16
#define NKV 4
#define NHD 64
#define SP 68   // smem row pitch for 64-wide tiles (16B aligned)

// ---------------- scratch (static device globals; no allocation) -------------
__device__ float g_q[(size_t)NB * NS * ND];          // [B*S, H*HD]  33.5 MB
__device__ float g_k[(size_t)NB * NS * NKV * NHD];   // [B*S, KV*HD]  8.4 MB
__device__ float g_v[(size_t)NB * NS * NKV * NHD];
__device__ float g_o[(size_t)NB * NS * ND];          // attention out, [B*S, H*HD]

// ---------------- SGEMM: C[M,N] = A[M,K] @ B[K,N], row-major -----------------
// Requires M%128==0, N%128==0, K%8==0 (true for all calls here).
__global__ __launch_bounds__(256) void sgemm_kernel(const float* __restrict__ A,
                                                    const float* __restrict__ B,
                                                    float* __restrict__ C,
                                                    int M, int N, int K)
{
    __shared__ float As[8][132];   // transposed A tile, padded (conflict-free)
    __shared__ float Bs[8][128];

    const int tid = threadIdx.x;
    const int bm = blockIdx.y, bn = blockIdx.x;
    const int ty = tid >> 4, tx = tid & 15;

    const int a_row = tid >> 1;
    const int a_c4  = (tid & 1) * 4;
    const int b_row = tid >> 5;
    const int b_col = (tid & 31) * 4;

    const float* Aptr = A + (size_t)(bm * 128 + a_row) * K + a_c4;
    const float* Bptr = B + (size_t)b_row * N + (size_t)bn * 128 + b_col;

    float acc[8][8];
#pragma unroll
    for (int i = 0; i < 8; i++)
#pragma unroll
        for (int j = 0; j < 8; j++) acc[i][j] = 0.f;

    for (int kt = 0; kt < K; kt += 8) {
        float4 av = *(const float4*)(Aptr + kt);
        float4 bv = *(const float4*)(Bptr + (size_t)kt * N);
        As[a_c4 + 0][a_row] = av.x;
        As[a_c4 + 1][a_row] = av.y;
        As[a_c4 + 2][a_row] = av.z;
        As[a_c4 + 3][a_row] = av.w;
        *(float4*)&Bs[b_row][b_col] = bv;
        __syncthreads();

#pragma unroll
        for (int k = 0; k < 8; k++) {
            float4 a0 = *(const float4*)&As[k][ty * 4];
            float4 a1 = *(const float4*)&As[k][ty * 4 + 64];
            float4 b0 = *(const float4*)&Bs[k][tx * 4];
            float4 b1 = *(const float4*)&Bs[k][tx * 4 + 64];
            float ar[8] = {a0.x, a0.y, a0.z, a0.w, a1.x, a1.y, a1.z, a1.w};
            float br[8] = {b0.x, b0.y, b0.z, b0.w, b1.x, b1.y, b1.z, b1.w};
#pragma unroll
            for (int i = 0; i < 8; i++)
#pragma unroll
                for (int j = 0; j < 8; j++)
                    acc[i][j] += ar[i] * br[j];
        }
        __syncthreads();
    }

#pragma unroll
    for (int ih = 0; ih < 2; ih++)
#pragma unroll
        for (int i = 0; i < 4; i++) {
            int row = bm * 128 + ih * 64 + ty * 4 + i;
            float* Cp = C + (size_t)row * N + (size_t)bn * 128;
            int r = ih * 4 + i;
            *(float4*)(Cp + tx * 4)      = make_float4(acc[r][0], acc[r][1], acc[r][2], acc[r][3]);
            *(float4*)(Cp + 64 + tx * 4) = make_float4(acc[r][4], acc[r][5], acc[r][6], acc[r][7]);
        }
}

// ---------------- Flash attention with ALiBi (non-causal, full) --------------
// grid = (S/64, H, B), block = 256 (16x16). Each thread owns rows {ty,ty+16,
// ty+32,ty+48} x cols {tx,tx+16,tx+32,tx+48} of the 64x64 tile (strided so all
// smem reads are broadcast / stride-1 / at worst 2-way).
__global__ __launch_bounds__(256) void attn_kernel()
{
    extern __shared__ float sm[];
    float* Qs = sm;               // [64][SP]
    float* KP = sm + 64 * SP;     // K chunk, then reused for P
    float* Vs = sm + 2 * 64 * SP; // V chunk

    const int qb = blockIdx.x;
    const int h  = blockIdx.y;
    const int b  = blockIdx.z;
    const int kvh = h >> 2;                  // h / GROUPS
    const int tid = threadIdx.x;
    const int ty = tid >> 4, tx = tid & 15;

    const float scale = 0.125f;              // 64^-0.5
    const float slope = exp2f(-0.5f * (float)(h + 1));

    // load Q tile [64 x 64]
    {
        const float* qbase = g_q + (size_t)(b * NS + qb * 64) * ND + h * NHD;
#pragma unroll
        for (int i = 0; i < 4; i++) {
            int lin = i * 256 + tid;
            int row = lin >> 4;
            int c4  = (lin & 15) * 4;
            float4 v = *(const float4*)(qbase + (size_t)row * ND + c4);
            *(float4*)(Qs + row * SP + c4) = v;
        }
    }

    float m_i[4], l_i[4], o[4][4];
#pragma unroll
    for (int i = 0; i < 4; i++) {
        m_i[i] = -INFINITY; l_i[i] = 0.f;
#pragma unroll
        for (int j = 0; j < 4; j++) o[i][j] = 0.f;
    }

    for (int kt = 0; kt < NS / 64; kt++) {
        __syncthreads();  // previous iteration done with KP/Vs

        // load K and V chunks [64 x 64]
        const float* kbase = g_k + (size_t)(b * NS + kt * 64) * (NKV * NHD) + kvh * NHD;
        const float* vbase = g_v + (size_t)(b * NS + kt * 64) * (NKV * NHD) + kvh * NHD;
#pragma unroll
        for (int i = 0; i < 4; i++) {
            int lin = i * 256 + tid;
            int row = lin >> 4;
            int c4  = (lin & 15) * 4;
            float4 kv4 = *(const float4*)(kbase + (size_t)row * (NKV * NHD) + c4);
            *(float4*)(KP + row * SP + c4) = kv4;
            float4 vv4 = *(const float4*)(vbase + (size_t)row * (NKV * NHD) + c4);
            *(float4*)(Vs + row * SP + c4) = vv4;
        }
        __syncthreads();

        // scores s[i][j] = Q[ty+16i] . K[tx+16j]
        float s[4][4];
#pragma unroll
        for (int i = 0; i < 4; i++)
#pragma unroll
            for (int j = 0; j < 4; j++) s[i][j] = 0.f;

#pragma unroll 8
        for (int k = 0; k < 64; k++) {
            float a0 = Qs[(ty +  0) * SP + k];
            float a1 = Qs[(ty + 16) * SP + k];
            float a2 = Qs[(ty + 32) * SP + k];
            float a3 = Qs[(ty + 48) * SP + k];
            float b0 = KP[(tx +  0) * SP + k];
            float b1 = KP[(tx + 16) * SP + k];
            float b2 = KP[(tx + 32) * SP + k];
            float b3 = KP[(tx + 48) * SP + k];
            s[0][0] += a0 * b0; s[0][1] += a0 * b1; s[0][2] += a0 * b2; s[0][3] += a0 * b3;
            s[1][0] += a1 * b0; s[1][1] += a1 * b1; s[1][2] += a1 * b2; s[1][3] += a1 * b3;
            s[2][0] += a2 * b0; s[2][1] += a2 * b1; s[2][2] += a2 * b2; s[2][3] += a2 * b3;
            s[3][0] += a3 * b0; s[3][1] += a3 * b1; s[3][2] += a3 * b2; s[3][3] += a3 * b3;
        }

        // scale + ALiBi bias, row max
        float rmax[4];
#pragma unroll
        for (int i = 0; i < 4; i++) {
            float ip = (float)(qb * 64 + ty + 16 * i);
#pragma unroll
            for (int j = 0; j < 4; j++) {
                float jp = (float)(kt * 64 + tx + 16 * j);
                s[i][j] = s[i][j] * scale + slope * (jp - ip);
            }
            rmax[i] = fmaxf(fmaxf(s[i][0], s[i][1]), fmaxf(s[i][2], s[i][3]));
        }
        // reduce row max across the 16-lane row group (stays inside each half-warp)
#pragma unroll
        for (int i = 0; i < 4; i++) {
            rmax[i] = fmaxf(rmax[i], __shfl_xor_sync(0xffffffffu, rmax[i], 8));
            rmax[i] = fmaxf(rmax[i], __shfl_xor_sync(0xffffffffu, rmax[i], 4));
            rmax[i] = fmaxf(rmax[i], __shfl_xor_sync(0xffffffffu, rmax[i], 2));
            rmax[i] = fmaxf(rmax[i], __shfl_xor_sync(0xffffffffu, rmax[i], 1));
        }

        float rsum[4];
#pragma unroll
        for (int i = 0; i < 4; i++) {
            float mnew = fmaxf(m_i[i], rmax[i]);
            float fac  = __expf(m_i[i] - mnew);
            m_i[i] = mnew;
            float rs = 0.f;
#pragma unroll
            for (int j = 0; j < 4; j++) {
                s[i][j] = __expf(s[i][j] - mnew);
                rs += s[i][j];
            }
            rsum[i] = rs;
            l_i[i] *= fac;
#pragma unroll
            for (int j = 0; j < 4; j++) o[i][j] *= fac;
        }
#pragma unroll
        for (int i = 0; i < 4; i++) {
            rsum[i] += __shfl_xor_sync(0xffffffffu, rsum[i], 8);
            rsum[i] += __shfl_xor_sync(0xffffffffu, rsum[i], 4);
            rsum[i] += __shfl_xor_sync(0xffffffffu, rsum[i], 2);
            rsum[i] += __shfl_xor_sync(0xffffffffu, rsum[i], 1);
            l_i[i] += rsum[i];
        }

        __syncthreads();  // everyone done reading K from KP
        // write P into KP
#pragma unroll
        for (int i = 0; i < 4; i++)
#pragma unroll
            for (int j = 0; j < 4; j++)
                KP[(ty + 16 * i) * SP + tx + 16 * j] = s[i][j];
        __syncthreads();

        // O += P @ V
#pragma unroll 8
        for (int c = 0; c < 64; c++) {
            float p0 = KP[(ty +  0) * SP + c];
            float p1 = KP[(ty + 16) * SP + c];
            float p2 = KP[(ty + 32) * SP + c];
            float p3 = KP[(ty + 48) * SP + c];
            float v0 = Vs[c * SP + tx +  0];
            float v1 = Vs[c * SP + tx + 16];
            float v2 = Vs[c * SP + tx + 32];
            float v3 = Vs[c * SP + tx + 48];
            o[0][0] += p0 * v0; o[0][1] += p0 * v1; o[0][2] += p0 * v2; o[0][3] += p0 * v3;
            o[1][0] += p1 * v0; o[1][1] += p1 * v1; o[1][2] += p1 * v2; o[1][3] += p1 * v3;
            o[2][0] += p2 * v0; o[2][1] += p2 * v1; o[2][2] += p2 * v2; o[2][3] += p2 * v3;
            o[3][0] += p3 * v0; o[3][1] += p3 * v1; o[3][2] += p3 * v2; o[3][3] += p3 * v3;
        }
    }

    // epilogue: normalize and store to [B*S, H*HD]
    float* obase = g_o + (size_t)(b * NS + qb * 64) * ND + h * NHD;
#pragma unroll
    for (int i = 0; i < 4; i++) {
        float inv = 1.f / l_i[i];
#pragma unroll
        for (int j = 0; j < 4; j++)
            obase[(size_t)(ty + 16 * i) * ND + tx + 16 * j] = o[i][j] * inv;
    }
}

// ---------------- launch ------------------------------------------------------
extern "C" void kernel_launch(void* const* d_in, const int* in_sizes, int n_in,
                              void* d_out, int out_size)
{
    const float* x  = (const float*)d_in[0];
    const float* Wq = (const float*)d_in[1];
    const float* Wk = (const float*)d_in[2];
    const float* Wv = (const float*)d_in[3];
    const float* Wo = (const float*)d_in[4];
    float* out = (float*)d_out;

    float *q, *k, *v, *o;
    cudaGetSymbolAddress((void**)&q, g_q);
    cudaGetSymbolAddress((void**)&k, g_k);
    cudaGetSymbolAddress((void**)&v, g_v);
    cudaGetSymbolAddress((void**)&o, g_o);

    const int smem_attn = 3 * 64 * SP * sizeof(float);  // 52224 B
    cudaFuncSetAttribute(attn_kernel, cudaFuncAttributeMaxDynamicSharedMemorySize, smem_attn);

    const int M = NB * NS;  // 8192

    sgemm_kernel<<<dim3(ND / 128, M / 128), 256>>>(x, Wq, q, M, ND, ND);
    sgemm_kernel<<<dim3((NKV * NHD) / 128, M / 128), 256>>>(x, Wk, k, M, NKV * NHD, ND);
    sgemm_kernel<<<dim3((NKV * NHD) / 128, M / 128), 256>>>(x, Wv, v, M, NKV * NHD, ND);
    attn_kernel<<<dim3(NS / 64, NH, NB), 256, smem_attn>>>();
    sgemm_kernel<<<dim3(ND / 128, M / 128), 256>>>(o, Wo, out, M, ND, ND);
}

// round 3
// speedup vs baseline: 2.4919x; 2.4919x over previous
#include <cuda_runtime.h>
#include <math.h>
#include <cstdint>

#define NB 4
#define NS 2048
#define ND 1024
#define NH 16
#define NKV 4
#define NHD 64
#define MTOT (NB * NS)   // 8192

// ---------------- scratch (static device globals; no allocation) -------------
__device__ float g_q[(size_t)MTOT * ND];
__device__ float g_k[(size_t)MTOT * NKV * NHD];
__device__ float g_v[(size_t)MTOT * NKV * NHD];
__device__ float g_o[(size_t)MTOT * ND];

// ---------------- helpers -----------------------------------------------------
__device__ __forceinline__ uint32_t f2tf(float f) {
    uint32_t r;
    asm("cvt.rna.tf32.f32 %0, %1;" : "=r"(r) : "f"(f));
    return r;
}
// D += A(16x8) * B(8x8), tf32 inputs, fp32 accum.
// A frag: a0=[g][t], a1=[g+8][t], a2=[g][t+4], a3=[g+8][t+4]   (g=lane>>2, t=lane&3)
// B frag (kxn): b0=[t][g], b1=[t+4][g]
// C frag: c0=[g][2t], c1=[g][2t+1], c2=[g+8][2t], c3=[g+8][2t+1]
__device__ __forceinline__ void mma8(float* c, const uint32_t* a, const uint32_t* b) {
    asm volatile(
        "mma.sync.aligned.m16n8k8.row.col.f32.tf32.tf32.f32 "
        "{%0,%1,%2,%3}, {%4,%5,%6,%7}, {%8,%9}, {%0,%1,%2,%3};"
        : "+f"(c[0]), "+f"(c[1]), "+f"(c[2]), "+f"(c[3])
        : "r"(a[0]), "r"(a[1]), "r"(a[2]), "r"(a[3]), "r"(b[0]), "r"(b[1]));
}

// ---------------- tf32 GEMM: C[M,N] = A[M,K] @ W[K,N] ------------------------
// Block 256 thr (8 warps), tile 128x128x16. Warp tile 32x64.
#define AP 20    // As pitch (conflict-free for frag loads)
#define WP 132   // Ws pitch

__global__ __launch_bounds__(256) void tgemm(const float* __restrict__ A,
                                             const float* __restrict__ W,
                                             float* __restrict__ C,
                                             int M, int N, int K) {
    __shared__ uint32_t As[128 * AP];
    __shared__ uint32_t Ws[16 * WP];

    const int tid = threadIdx.x, wid = tid >> 5, lane = tid & 31;
    const int g = lane >> 2, tg = lane & 3;
    const int bm = blockIdx.y, bn = blockIdx.x;
    const int wm = wid >> 1, wn = wid & 1;

    float acc[2][8][4];
#pragma unroll
    for (int i = 0; i < 2; i++)
#pragma unroll
        for (int j = 0; j < 8; j++)
#pragma unroll
            for (int r = 0; r < 4; r++) acc[i][j][r] = 0.f;

    for (int kt = 0; kt < K; kt += 16) {
        // load A tile [128 x 16] -> As[m][k]
#pragma unroll
        for (int rep = 0; rep < 2; rep++) {
            int idx = rep * 256 + tid;
            int m = idx >> 2, kg = (idx & 3) * 4;
            float4 v = *(const float4*)(A + (size_t)(bm * 128 + m) * K + kt + kg);
            *(uint4*)&As[m * AP + kg] = make_uint4(f2tf(v.x), f2tf(v.y), f2tf(v.z), f2tf(v.w));
        }
        // load W tile [16 x 128] -> Ws[k][n]
#pragma unroll
        for (int rep = 0; rep < 2; rep++) {
            int idx = rep * 256 + tid;
            int k = idx >> 5, ng = (idx & 31) * 4;
            float4 v = *(const float4*)(W + (size_t)(kt + k) * N + bn * 128 + ng);
            *(uint4*)&Ws[k * WP + ng] = make_uint4(f2tf(v.x), f2tf(v.y), f2tf(v.z), f2tf(v.w));
        }
        __syncthreads();

#pragma unroll
        for (int ks = 0; ks < 2; ks++) {
            const int k0 = ks * 8;
            uint32_t a[2][4];
#pragma unroll
            for (int mt = 0; mt < 2; mt++) {
                int rm = wm * 32 + mt * 16;
                a[mt][0] = As[(rm + g) * AP + k0 + tg];
                a[mt][1] = As[(rm + g + 8) * AP + k0 + tg];
                a[mt][2] = As[(rm + g) * AP + k0 + tg + 4];
                a[mt][3] = As[(rm + g + 8) * AP + k0 + tg + 4];
            }
#pragma unroll
            for (int nt = 0; nt < 8; nt++) {
                uint32_t b[2];
                int cn = wn * 64 + nt * 8 + g;
                b[0] = Ws[(k0 + tg) * WP + cn];
                b[1] = Ws[(k0 + tg + 4) * WP + cn];
                mma8(acc[0][nt], a[0], b);
                mma8(acc[1][nt], a[1], b);
            }
        }
        __syncthreads();
    }

    // epilogue
#pragma unroll
    for (int mt = 0; mt < 2; mt++)
#pragma unroll
        for (int nt = 0; nt < 8; nt++) {
            int row = bm * 128 + wm * 32 + mt * 16 + g;
            int col = bn * 128 + wn * 64 + nt * 8 + 2 * tg;
            *(float2*)(C + (size_t)row * N + col) =
                make_float2(acc[mt][nt][0], acc[mt][nt][1]);
            *(float2*)(C + (size_t)(row + 8) * N + col) =
                make_float2(acc[mt][nt][2], acc[mt][nt][3]);
        }
}

// ---------------- Flash attention with ALiBi on tf32 mma ---------------------
// Block 128 thr (4 warps). Each block: 64 q rows x full KV loop (chunks of 64).
// Warp w owns rows [w*16, w*16+16).
#define QP 68
__global__ __launch_bounds__(128) void attn_mma() {
    extern __shared__ uint32_t sm4[];
    uint32_t* Qs = sm4;               // [64][QP] tf32
    uint32_t* Ks = sm4 + 64 * QP;     // [64][QP] tf32 (row = kv pos, col = hd)
    uint32_t* Vs = sm4 + 2 * 64 * QP; // [64][QP] tf32
    uint32_t* Ps = sm4 + 3 * 64 * QP; // [64][QP] tf32 (warp-private rows)

    const int qb = blockIdx.x, h = blockIdx.y, b = blockIdx.z;
    const int kvh = h >> 2;
    const int tid = threadIdx.x, w = tid >> 5, lane = tid & 31;
    const int g = lane >> 2, tg = lane & 3;

    const float scale = 0.125f;
    const float slope = exp2f(-0.5f * (float)(h + 1));

    // load Q tile [64 x 64] -> tf32
    {
        const float* qbase = g_q + (size_t)(b * NS + qb * 64) * ND + h * NHD;
#pragma unroll
        for (int rep = 0; rep < 8; rep++) {
            int idx = rep * 128 + tid;
            int r = idx >> 4, cg = (idx & 15) * 4;
            float4 v = *(const float4*)(qbase + (size_t)r * ND + cg);
            *(uint4*)&Qs[r * QP + cg] = make_uint4(f2tf(v.x), f2tf(v.y), f2tf(v.z), f2tf(v.w));
        }
    }

    float m0 = -INFINITY, m1 = -INFINITY, l0 = 0.f, l1 = 0.f;
    float O[8][4];
#pragma unroll
    for (int i = 0; i < 8; i++)
#pragma unroll
        for (int j = 0; j < 4; j++) O[i][j] = 0.f;

    const float rowi0 = (float)(qb * 64 + w * 16 + g);
    const float rowi1 = rowi0 + 8.f;

    for (int kt = 0; kt < NS / 64; kt++) {
        __syncthreads();
        // load K, V chunks [64 x 64]
        const float* kbase = g_k + (size_t)(b * NS + kt * 64) * (NKV * NHD) + kvh * NHD;
        const float* vbase = g_v + (size_t)(b * NS + kt * 64) * (NKV * NHD) + kvh * NHD;
#pragma unroll
        for (int rep = 0; rep < 8; rep++) {
            int idx = rep * 128 + tid;
            int r = idx >> 4, cg = (idx & 15) * 4;
            float4 kv = *(const float4*)(kbase + (size_t)r * (NKV * NHD) + cg);
            *(uint4*)&Ks[r * QP + cg] = make_uint4(f2tf(kv.x), f2tf(kv.y), f2tf(kv.z), f2tf(kv.w));
            float4 vv = *(const float4*)(vbase + (size_t)r * (NKV * NHD) + cg);
            *(uint4*)&Vs[r * QP + cg] = make_uint4(f2tf(vv.x), f2tf(vv.y), f2tf(vv.z), f2tf(vv.w));
        }
        __syncthreads();

        // S[16 x 64] = Q_w @ K^T   (8 n-tiles, 8 k-steps)
        float S[8][4];
#pragma unroll
        for (int i = 0; i < 8; i++)
#pragma unroll
            for (int j = 0; j < 4; j++) S[i][j] = 0.f;

#pragma unroll
        for (int ks = 0; ks < 8; ks++) {
            const int k0 = ks * 8;
            uint32_t a[4];
            a[0] = Qs[(w * 16 + g) * QP + k0 + tg];
            a[1] = Qs[(w * 16 + g + 8) * QP + k0 + tg];
            a[2] = Qs[(w * 16 + g) * QP + k0 + tg + 4];
            a[3] = Qs[(w * 16 + g + 8) * QP + k0 + tg + 4];
#pragma unroll
            for (int nt = 0; nt < 8; nt++) {
                uint32_t bb[2];
                bb[0] = Ks[(nt * 8 + g) * QP + k0 + tg];
                bb[1] = Ks[(nt * 8 + g) * QP + k0 + tg + 4];
                mma8(S[nt], a, bb);
            }
        }

        // scale + ALiBi + row max
        float mx0 = -INFINITY, mx1 = -INFINITY;
#pragma unroll
        for (int nt = 0; nt < 8; nt++) {
            float j0 = (float)(kt * 64 + nt * 8 + 2 * tg);
            S[nt][0] = S[nt][0] * scale + slope * (j0 - rowi0);
            S[nt][1] = S[nt][1] * scale + slope * (j0 + 1.f - rowi0);
            S[nt][2] = S[nt][2] * scale + slope * (j0 - rowi1);
            S[nt][3] = S[nt][3] * scale + slope * (j0 + 1.f - rowi1);
            mx0 = fmaxf(mx0, fmaxf(S[nt][0], S[nt][1]));
            mx1 = fmaxf(mx1, fmaxf(S[nt][2], S[nt][3]));
        }
        mx0 = fmaxf(mx0, __shfl_xor_sync(0xffffffffu, mx0, 1));
        mx0 = fmaxf(mx0, __shfl_xor_sync(0xffffffffu, mx0, 2));
        mx1 = fmaxf(mx1, __shfl_xor_sync(0xffffffffu, mx1, 1));
        mx1 = fmaxf(mx1, __shfl_xor_sync(0xffffffffu, mx1, 2));

        float mn0 = fmaxf(m0, mx0), mn1 = fmaxf(m1, mx1);
        float f0 = __expf(m0 - mn0), f1 = __expf(m1 - mn1);
        m0 = mn0; m1 = mn1;

        float rs0 = 0.f, rs1 = 0.f;
#pragma unroll
        for (int nt = 0; nt < 8; nt++) {
            S[nt][0] = __expf(S[nt][0] - mn0);
            S[nt][1] = __expf(S[nt][1] - mn0);
            S[nt][2] = __expf(S[nt][2] - mn1);
            S[nt][3] = __expf(S[nt][3] - mn1);
            rs0 += S[nt][0] + S[nt][1];
            rs1 += S[nt][2] + S[nt][3];
        }
        rs0 += __shfl_xor_sync(0xffffffffu, rs0, 1);
        rs0 += __shfl_xor_sync(0xffffffffu, rs0, 2);
        rs1 += __shfl_xor_sync(0xffffffffu, rs1, 1);
        rs1 += __shfl_xor_sync(0xffffffffu, rs1, 2);
        l0 = l0 * f0 + rs0;
        l1 = l1 * f1 + rs1;

#pragma unroll
        for (int nt = 0; nt < 8; nt++) {
            O[nt][0] *= f0; O[nt][1] *= f0;
            O[nt][2] *= f1; O[nt][3] *= f1;
        }

        // write P (tf32) to warp-private smem rows
#pragma unroll
        for (int nt = 0; nt < 8; nt++) {
            Ps[(w * 16 + g) * QP + nt * 8 + 2 * tg]     = f2tf(S[nt][0]);
            Ps[(w * 16 + g) * QP + nt * 8 + 2 * tg + 1] = f2tf(S[nt][1]);
            Ps[(w * 16 + g + 8) * QP + nt * 8 + 2 * tg]     = f2tf(S[nt][2]);
            Ps[(w * 16 + g + 8) * QP + nt * 8 + 2 * tg + 1] = f2tf(S[nt][3]);
        }
        __syncwarp();

        // O += P @ V   (k = kv in chunks of 8, n = hd)
#pragma unroll
        for (int ks = 0; ks < 8; ks++) {
            const int k0 = ks * 8;
            uint32_t a[4];
            a[0] = Ps[(w * 16 + g) * QP + k0 + tg];
            a[1] = Ps[(w * 16 + g + 8) * QP + k0 + tg];
            a[2] = Ps[(w * 16 + g) * QP + k0 + tg + 4];
            a[3] = Ps[(w * 16 + g + 8) * QP + k0 + tg + 4];
#pragma unroll
            for (int nt = 0; nt < 8; nt++) {
                uint32_t bb[2];
                bb[0] = Vs[(k0 + tg) * QP + nt * 8 + g];
                bb[1] = Vs[(k0 + tg + 4) * QP + nt * 8 + g];
                mma8(O[nt], a, bb);
            }
        }
        __syncwarp();  // Ps reused next chunk
    }

    // epilogue: normalize + store
    float inv0 = 1.f / l0, inv1 = 1.f / l1;
    float* ob = g_o + (size_t)(b * NS + qb * 64 + w * 16 + g) * ND + h * NHD;
#pragma unroll
    for (int nt = 0; nt < 8; nt++) {
        *(float2*)(ob + nt * 8 + 2 * tg) = make_float2(O[nt][0] * inv0, O[nt][1] * inv0);
        *(float2*)(ob + (size_t)8 * ND + nt * 8 + 2 * tg) =
            make_float2(O[nt][2] * inv1, O[nt][3] * inv1);
    }
}

// ---------------- launch ------------------------------------------------------
extern "C" void kernel_launch(void* const* d_in, const int* in_sizes, int n_in,
                              void* d_out, int out_size) {
    const float* x  = (const float*)d_in[0];
    const float* Wq = (const float*)d_in[1];
    const float* Wk = (const float*)d_in[2];
    const float* Wv = (const float*)d_in[3];
    const float* Wo = (const float*)d_in[4];
    float* out = (float*)d_out;

    float *q, *k, *v, *o;
    cudaGetSymbolAddress((void**)&q, g_q);
    cudaGetSymbolAddress((void**)&k, g_k);
    cudaGetSymbolAddress((void**)&v, g_v);
    cudaGetSymbolAddress((void**)&o, g_o);

    const int smem_attn = 4 * 64 * QP * sizeof(uint32_t);  // 69632
    cudaFuncSetAttribute(attn_mma, cudaFuncAttributeMaxDynamicSharedMemorySize, smem_attn);

    tgemm<<<dim3(ND / 128, MTOT / 128), 256>>>(x, Wq, q, MTOT, ND, ND);
    tgemm<<<dim3(256 / 128, MTOT / 128), 256>>>(x, Wk, k, MTOT, 256, ND);
    tgemm<<<dim3(256 / 128, MTOT / 128), 256>>>(x, Wv, v, MTOT, 256, ND);

    attn_mma<<<dim3(NS / 64, NH, NB), 128, smem_attn>>>();

    tgemm<<<dim3(ND / 128, MTOT / 128), 256>>>(o, Wo, out, MTOT, ND, ND);
}

// round 4
// speedup vs baseline: 3.3904x; 1.3605x over previous
#include <cuda_runtime.h>
#include <math.h>
#include <cstdint>

#define NB 4
#define NS 2048
#define ND 1024
#define NH 16
#define NKV 4
#define NHD 64
#define MTOT (NB * NS)   // 8192

// ---------------- scratch (static device globals; no allocation) -------------
__device__ float g_q[(size_t)MTOT * ND];
__device__ float g_k[(size_t)MTOT * NKV * NHD];
__device__ float g_v[(size_t)MTOT * NKV * NHD];
__device__ float g_o[(size_t)MTOT * ND];

// ---------------- helpers -----------------------------------------------------
__device__ __forceinline__ uint32_t f2tf(float f) {
    uint32_t r;
    asm("cvt.rna.tf32.f32 %0, %1;" : "=r"(r) : "f"(f));
    return r;
}
__device__ __forceinline__ float ex2(float x) {
    float y;
    asm("ex2.approx.f32 %0, %1;" : "=f"(y) : "f"(x));
    return y;
}
// D += A(16x8) * B(8x8), tf32, fp32 accum.
// A frag: a0=[g][t], a1=[g+8][t], a2=[g][t+4], a3=[g+8][t+4]  (g=lane>>2,t=lane&3)
// B frag (kxn): b0=[t][g], b1=[t+4][g]
// C frag: c0=[g][2t], c1=[g][2t+1], c2=[g+8][2t], c3=[g+8][2t+1]
__device__ __forceinline__ void mma8(float* c, const uint32_t* a, const uint32_t* b) {
    asm volatile(
        "mma.sync.aligned.m16n8k8.row.col.f32.tf32.tf32.f32 "
        "{%0,%1,%2,%3}, {%4,%5,%6,%7}, {%8,%9}, {%0,%1,%2,%3};"
        : "+f"(c[0]), "+f"(c[1]), "+f"(c[2]), "+f"(c[3])
        : "r"(a[0]), "r"(a[1]), "r"(a[2]), "r"(a[3]), "r"(b[0]), "r"(b[1]));
}

// ---------------- tf32 GEMM: C = A[M,K] @ W[K,N], double-buffered ------------
#define AP 20    // A pitch: banks 20g+tg -> conflict-free
#define WPX 136  // W pitch: 136 % 32 = 8 -> banks 8t+g conflict-free

__device__ __forceinline__ void tgemm_body(const float* __restrict__ A,
                                           const float* __restrict__ W,
                                           float* __restrict__ C,
                                           int M, int N, int K,
                                           uint32_t (*As)[128 * AP],
                                           uint32_t (*Ws)[16 * WPX]) {
    const int tid = threadIdx.x, wid = tid >> 5, lane = tid & 31;
    const int g = lane >> 2, tg = lane & 3;
    const int bm = blockIdx.y, bn = blockIdx.x;
    const int wm = wid >> 1, wn = wid & 1;

    const int am = tid >> 2, akg = (tid & 3) * 4;          // A: row, col4 (rep adds 64 rows)
    const int wk = tid >> 5, wng = (tid & 31) * 4;         // W: row, col4 (rep adds 8 rows)
    const float* Ap = A + (size_t)(bm * 128 + am) * K + akg;
    const float* Wp = W + (size_t)wk * N + bn * 128 + wng;

    float acc[2][8][4];
#pragma unroll
    for (int i = 0; i < 2; i++)
#pragma unroll
        for (int j = 0; j < 8; j++)
#pragma unroll
            for (int r = 0; r < 4; r++) acc[i][j][r] = 0.f;

    const int nk = K / 16;

    // preload tile 0
    {
        float4 a0 = *(const float4*)(Ap);
        float4 a1 = *(const float4*)(Ap + (size_t)64 * K);
        float4 w0 = *(const float4*)(Wp);
        float4 w1 = *(const float4*)(Wp + (size_t)8 * N);
        *(uint4*)&As[0][am * AP + akg] = make_uint4(f2tf(a0.x), f2tf(a0.y), f2tf(a0.z), f2tf(a0.w));
        *(uint4*)&As[0][(am + 64) * AP + akg] = make_uint4(f2tf(a1.x), f2tf(a1.y), f2tf(a1.z), f2tf(a1.w));
        *(uint4*)&Ws[0][wk * WPX + wng] = make_uint4(f2tf(w0.x), f2tf(w0.y), f2tf(w0.z), f2tf(w0.w));
        *(uint4*)&Ws[0][(wk + 8) * WPX + wng] = make_uint4(f2tf(w1.x), f2tf(w1.y), f2tf(w1.z), f2tf(w1.w));
    }
    __syncthreads();

    for (int kt = 0; kt < nk; kt++) {
        const int buf = kt & 1;
        float4 a0, a1, w0, w1;
        const bool more = (kt + 1) < nk;
        if (more) {
            const float* ap = Ap + (kt + 1) * 16;
            const float* wp = Wp + (size_t)(kt + 1) * 16 * N;
            a0 = *(const float4*)(ap);
            a1 = *(const float4*)(ap + (size_t)64 * K);
            w0 = *(const float4*)(wp);
            w1 = *(const float4*)(wp + (size_t)8 * N);
        }

#pragma unroll
        for (int ks = 0; ks < 2; ks++) {
            const int k0 = ks * 8;
            uint32_t a[2][4];
#pragma unroll
            for (int mt = 0; mt < 2; mt++) {
                int rm = wm * 32 + mt * 16;
                a[mt][0] = As[buf][(rm + g) * AP + k0 + tg];
                a[mt][1] = As[buf][(rm + g + 8) * AP + k0 + tg];
                a[mt][2] = As[buf][(rm + g) * AP + k0 + tg + 4];
                a[mt][3] = As[buf][(rm + g + 8) * AP + k0 + tg + 4];
            }
#pragma unroll
            for (int nt = 0; nt < 8; nt++) {
                uint32_t b[2];
                int cn = wn * 64 + nt * 8 + g;
                b[0] = Ws[buf][(k0 + tg) * WPX + cn];
                b[1] = Ws[buf][(k0 + tg + 4) * WPX + cn];
                mma8(acc[0][nt], a[0], b);
                mma8(acc[1][nt], a[1], b);
            }
        }

        if (more) {
            const int nb = buf ^ 1;
            *(uint4*)&As[nb][am * AP + akg] = make_uint4(f2tf(a0.x), f2tf(a0.y), f2tf(a0.z), f2tf(a0.w));
            *(uint4*)&As[nb][(am + 64) * AP + akg] = make_uint4(f2tf(a1.x), f2tf(a1.y), f2tf(a1.z), f2tf(a1.w));
            *(uint4*)&Ws[nb][wk * WPX + wng] = make_uint4(f2tf(w0.x), f2tf(w0.y), f2tf(w0.z), f2tf(w0.w));
            *(uint4*)&Ws[nb][(wk + 8) * WPX + wng] = make_uint4(f2tf(w1.x), f2tf(w1.y), f2tf(w1.z), f2tf(w1.w));
        }
        __syncthreads();
    }

#pragma unroll
    for (int mt = 0; mt < 2; mt++)
#pragma unroll
        for (int nt = 0; nt < 8; nt++) {
            int row = bm * 128 + wm * 32 + mt * 16 + g;
            int col = bn * 128 + wn * 64 + nt * 8 + 2 * tg;
            *(float2*)(C + (size_t)row * N + col) = make_float2(acc[mt][nt][0], acc[mt][nt][1]);
            *(float2*)(C + (size_t)(row + 8) * N + col) = make_float2(acc[mt][nt][2], acc[mt][nt][3]);
        }
}

__global__ __launch_bounds__(256) void tgemm(const float* __restrict__ A,
                                             const float* __restrict__ W,
                                             float* __restrict__ C,
                                             int M, int N, int K) {
    __shared__ uint32_t As[2][128 * AP];
    __shared__ uint32_t Ws[2][16 * WPX];
    tgemm_body(A, W, C, M, N, K, As, Ws);
}

__global__ __launch_bounds__(256) void tgemm_dual(const float* __restrict__ A,
                                                  const float* __restrict__ W0,
                                                  const float* __restrict__ W1,
                                                  float* __restrict__ C0,
                                                  float* __restrict__ C1,
                                                  int M, int N, int K) {
    __shared__ uint32_t As[2][128 * AP];
    __shared__ uint32_t Ws[2][16 * WPX];
    const float* W = blockIdx.z ? W1 : W0;
    float* C = blockIdx.z ? C1 : C0;
    tgemm_body(A, W, C, M, N, K, As, Ws);
}

// ---------------- Flash attention, tf32 mma, 32-row warp tiles ---------------
// Block 128 thr (4 warps); q-tile 128 rows (32/warp); kv chunks of 64.
#define QP 68    // pitch for Q/K/P (row-major frags conflict-free)
#define VP 72    // pitch for V (k-major b-frags conflict-free: banks 8t+g)
#define SM_Q 0
#define SM_K (128 * QP)
#define SM_V (SM_K + 64 * QP)
#define SM_P (SM_V + 64 * VP)
#define SM_TOT (SM_P + 128 * QP)        // words

__global__ __launch_bounds__(128) void attn_mma() {
    extern __shared__ uint32_t sm4[];
    uint32_t* Qs = sm4 + SM_Q;
    uint32_t* Ks = sm4 + SM_K;
    uint32_t* Vs = sm4 + SM_V;
    uint32_t* Ps = sm4 + SM_P;

    const int qb = blockIdx.x, h = blockIdx.y, b = blockIdx.z;
    const int kvh = h >> 2;
    const int tid = threadIdx.x, w = tid >> 5, lane = tid & 31;
    const int g = lane >> 2, tg = lane & 3;

    const float LOG2E = 1.4426950408889634f;
    const float sc2 = 0.125f * LOG2E;
    const float slope2 = ex2(-0.5f * (float)(h + 1)) * LOG2E;

    // load Q tile [128 x 64]
    {
        const float* qbase = g_q + (size_t)(b * NS + qb * 128) * ND + h * NHD;
#pragma unroll
        for (int rep = 0; rep < 16; rep++) {
            int idx = rep * 128 + tid;
            int r = idx >> 4, cg = (idx & 15) * 4;
            float4 v = *(const float4*)(qbase + (size_t)r * ND + cg);
            *(uint4*)&Qs[r * QP + cg] = make_uint4(f2tf(v.x), f2tf(v.y), f2tf(v.z), f2tf(v.w));
        }
    }

    float m[4], l[4], O[2][8][4];
#pragma unroll
    for (int i = 0; i < 4; i++) { m[i] = -INFINITY; l[i] = 0.f; }
#pragma unroll
    for (int mt = 0; mt < 2; mt++)
#pragma unroll
        for (int nt = 0; nt < 8; nt++)
#pragma unroll
            for (int r = 0; r < 4; r++) O[mt][nt][r] = 0.f;

    float rowi[4];
#pragma unroll
    for (int mt = 0; mt < 2; mt++) {
        rowi[2 * mt]     = (float)(qb * 128 + w * 32 + mt * 16 + g);
        rowi[2 * mt + 1] = rowi[2 * mt] + 8.f;
    }

    for (int kt = 0; kt < NS / 64; kt++) {
        __syncthreads();
        const float* kbase = g_k + (size_t)(b * NS + kt * 64) * (NKV * NHD) + kvh * NHD;
        const float* vbase = g_v + (size_t)(b * NS + kt * 64) * (NKV * NHD) + kvh * NHD;
#pragma unroll
        for (int rep = 0; rep < 8; rep++) {
            int idx = rep * 128 + tid;
            int r = idx >> 4, cg = (idx & 15) * 4;
            float4 kv = *(const float4*)(kbase + (size_t)r * (NKV * NHD) + cg);
            *(uint4*)&Ks[r * QP + cg] = make_uint4(f2tf(kv.x), f2tf(kv.y), f2tf(kv.z), f2tf(kv.w));
            float4 vv = *(const float4*)(vbase + (size_t)r * (NKV * NHD) + cg);
            *(uint4*)&Vs[r * VP + cg] = make_uint4(f2tf(vv.x), f2tf(vv.y), f2tf(vv.z), f2tf(vv.w));
        }
        __syncthreads();

        // S[2][8][4] = Q_w @ K^T
        float S[2][8][4];
#pragma unroll
        for (int mt = 0; mt < 2; mt++)
#pragma unroll
            for (int nt = 0; nt < 8; nt++)
#pragma unroll
                for (int r = 0; r < 4; r++) S[mt][nt][r] = 0.f;

#pragma unroll
        for (int ks = 0; ks < 8; ks++) {
            const int k0 = ks * 8;
            uint32_t a[2][4];
#pragma unroll
            for (int mt = 0; mt < 2; mt++) {
                int rb = w * 32 + mt * 16;
                a[mt][0] = Qs[(rb + g) * QP + k0 + tg];
                a[mt][1] = Qs[(rb + g + 8) * QP + k0 + tg];
                a[mt][2] = Qs[(rb + g) * QP + k0 + tg + 4];
                a[mt][3] = Qs[(rb + g + 8) * QP + k0 + tg + 4];
            }
#pragma unroll
            for (int nt = 0; nt < 8; nt++) {
                uint32_t bb[2];
                bb[0] = Ks[(nt * 8 + g) * QP + k0 + tg];
                bb[1] = Ks[(nt * 8 + g) * QP + k0 + tg + 4];
                mma8(S[0][nt], a[0], bb);
                mma8(S[1][nt], a[1], bb);
            }
        }

        // bias (log2 domain) + online softmax
#pragma unroll
        for (int mt = 0; mt < 2; mt++) {
            float mx0 = -INFINITY, mx1 = -INFINITY;
#pragma unroll
            for (int nt = 0; nt < 8; nt++) {
                float j0 = (float)(kt * 64 + nt * 8 + 2 * tg);
                S[mt][nt][0] = S[mt][nt][0] * sc2 + slope2 * (j0 - rowi[2 * mt]);
                S[mt][nt][1] = S[mt][nt][1] * sc2 + slope2 * (j0 + 1.f - rowi[2 * mt]);
                S[mt][nt][2] = S[mt][nt][2] * sc2 + slope2 * (j0 - rowi[2 * mt + 1]);
                S[mt][nt][3] = S[mt][nt][3] * sc2 + slope2 * (j0 + 1.f - rowi[2 * mt + 1]);
                mx0 = fmaxf(mx0, fmaxf(S[mt][nt][0], S[mt][nt][1]));
                mx1 = fmaxf(mx1, fmaxf(S[mt][nt][2], S[mt][nt][3]));
            }
            mx0 = fmaxf(mx0, __shfl_xor_sync(0xffffffffu, mx0, 1));
            mx0 = fmaxf(mx0, __shfl_xor_sync(0xffffffffu, mx0, 2));
            mx1 = fmaxf(mx1, __shfl_xor_sync(0xffffffffu, mx1, 1));
            mx1 = fmaxf(mx1, __shfl_xor_sync(0xffffffffu, mx1, 2));

            float mn0 = fmaxf(m[2 * mt], mx0), mn1 = fmaxf(m[2 * mt + 1], mx1);
            float f0 = ex2(m[2 * mt] - mn0), f1 = ex2(m[2 * mt + 1] - mn1);
            m[2 * mt] = mn0; m[2 * mt + 1] = mn1;

            float rs0 = 0.f, rs1 = 0.f;
#pragma unroll
            for (int nt = 0; nt < 8; nt++) {
                S[mt][nt][0] = ex2(S[mt][nt][0] - mn0);
                S[mt][nt][1] = ex2(S[mt][nt][1] - mn0);
                S[mt][nt][2] = ex2(S[mt][nt][2] - mn1);
                S[mt][nt][3] = ex2(S[mt][nt][3] - mn1);
                rs0 += S[mt][nt][0] + S[mt][nt][1];
                rs1 += S[mt][nt][2] + S[mt][nt][3];
            }
            rs0 += __shfl_xor_sync(0xffffffffu, rs0, 1);
            rs0 += __shfl_xor_sync(0xffffffffu, rs0, 2);
            rs1 += __shfl_xor_sync(0xffffffffu, rs1, 1);
            rs1 += __shfl_xor_sync(0xffffffffu, rs1, 2);
            l[2 * mt] = l[2 * mt] * f0 + rs0;
            l[2 * mt + 1] = l[2 * mt + 1] * f1 + rs1;

#pragma unroll
            for (int nt = 0; nt < 8; nt++) {
                O[mt][nt][0] *= f0; O[mt][nt][1] *= f0;
                O[mt][nt][2] *= f1; O[mt][nt][3] *= f1;
            }
        }

        // write P (tf32) to warp-private rows
#pragma unroll
        for (int mt = 0; mt < 2; mt++) {
            int rL = w * 32 + mt * 16 + g, rH = rL + 8;
#pragma unroll
            for (int nt = 0; nt < 8; nt++) {
                *(uint2*)&Ps[rL * QP + nt * 8 + 2 * tg] =
                    make_uint2(f2tf(S[mt][nt][0]), f2tf(S[mt][nt][1]));
                *(uint2*)&Ps[rH * QP + nt * 8 + 2 * tg] =
                    make_uint2(f2tf(S[mt][nt][2]), f2tf(S[mt][nt][3]));
            }
        }
        __syncwarp();

        // O += P @ V
#pragma unroll
        for (int ks = 0; ks < 8; ks++) {
            const int k0 = ks * 8;
            uint32_t a[2][4];
#pragma unroll
            for (int mt = 0; mt < 2; mt++) {
                int rb = w * 32 + mt * 16;
                a[mt][0] = Ps[(rb + g) * QP + k0 + tg];
                a[mt][1] = Ps[(rb + g + 8) * QP + k0 + tg];
                a[mt][2] = Ps[(rb + g) * QP + k0 + tg + 4];
                a[mt][3] = Ps[(rb + g + 8) * QP + k0 + tg + 4];
            }
#pragma unroll
            for (int nt = 0; nt < 8; nt++) {
                uint32_t bb[2];
                bb[0] = Vs[(k0 + tg) * VP + nt * 8 + g];
                bb[1] = Vs[(k0 + tg + 4) * VP + nt * 8 + g];
                mma8(O[0][nt], a[0], bb);
                mma8(O[1][nt], a[1], bb);
            }
        }
        __syncwarp();
    }

    // epilogue
#pragma unroll
    for (int mt = 0; mt < 2; mt++) {
        float inv0 = 1.f / l[2 * mt], inv1 = 1.f / l[2 * mt + 1];
        int rL = qb * 128 + w * 32 + mt * 16 + g;
        float* ob = g_o + (size_t)(b * NS + rL) * ND + h * NHD;
#pragma unroll
        for (int nt = 0; nt < 8; nt++) {
            *(float2*)(ob + nt * 8 + 2 * tg) =
                make_float2(O[mt][nt][0] * inv0, O[mt][nt][1] * inv0);
            *(float2*)(ob + (size_t)8 * ND + nt * 8 + 2 * tg) =
                make_float2(O[mt][nt][2] * inv1, O[mt][nt][3] * inv1);
        }
    }
}

// ---------------- launch ------------------------------------------------------
extern "C" void kernel_launch(void* const* d_in, const int* in_sizes, int n_in,
                              void* d_out, int out_size) {
    const float* x  = (const float*)d_in[0];
    const float* Wq = (const float*)d_in[1];
    const float* Wk = (const float*)d_in[2];
    const float* Wv = (const float*)d_in[3];
    const float* Wo = (const float*)d_in[4];
    float* out = (float*)d_out;

    float *q, *k, *v, *o;
    cudaGetSymbolAddress((void**)&q, g_q);
    cudaGetSymbolAddress((void**)&k, g_k);
    cudaGetSymbolAddress((void**)&v, g_v);
    cudaGetSymbolAddress((void**)&o, g_o);

    const int smem_attn = SM_TOT * sizeof(uint32_t);   // ~105 KB
    cudaFuncSetAttribute(attn_mma, cudaFuncAttributeMaxDynamicSharedMemorySize, smem_attn);

    tgemm<<<dim3(ND / 128, MTOT / 128), 256>>>(x, Wq, q, MTOT, ND, ND);
    tgemm_dual<<<dim3(256 / 128, MTOT / 128, 2), 256>>>(x, Wk, Wv, k, v, MTOT, 256, ND);

    attn_mma<<<dim3(NS / 128, NH, NB), 128, smem_attn>>>();

    tgemm<<<dim3(ND / 128, MTOT / 128), 256>>>(o, Wo, out, MTOT, ND, ND);
}

// round 5
// speedup vs baseline: 3.5364x; 1.0431x over previous
#include <cuda_runtime.h>
#include <math.h>
#include <cstdint>

#define NB 4
#define NS 2048
#define ND 1024
#define NH 16
#define NKV 4
#define NHD 64
#define MTOT (NB * NS)   // 8192

// ---------------- scratch (static device globals; no allocation) -------------
__device__ float g_q[(size_t)MTOT * ND];
__device__ float g_k[(size_t)MTOT * NKV * NHD];
__device__ float g_v[(size_t)MTOT * NKV * NHD];
__device__ float g_o[(size_t)MTOT * ND];

// ---------------- helpers -----------------------------------------------------
__device__ __forceinline__ uint32_t f2tf(float f) {
    uint32_t r;
    asm("cvt.rna.tf32.f32 %0, %1;" : "=r"(r) : "f"(f));
    return r;
}
__device__ __forceinline__ float ex2(float x) {
    float y;
    asm("ex2.approx.f32 %0, %1;" : "=f"(y) : "f"(x));
    return y;
}
__device__ __forceinline__ uint32_t smem_u32(const void* p) {
    uint32_t a;
    asm("{ .reg .u64 t; cvta.to.shared.u64 t, %1; cvt.u32.u64 %0, t; }" : "=r"(a) : "l"(p));
    return a;
}
__device__ __forceinline__ void ldmx4(uint32_t* r, uint32_t addr) {
    asm volatile("ldmatrix.sync.aligned.m8n8.x4.shared.b16 {%0,%1,%2,%3}, [%4];"
                 : "=r"(r[0]), "=r"(r[1]), "=r"(r[2]), "=r"(r[3]) : "r"(addr));
}
__device__ __forceinline__ void ldmx2(uint32_t* r, uint32_t addr) {
    asm volatile("ldmatrix.sync.aligned.m8n8.x2.shared.b16 {%0,%1}, [%2];"
                 : "=r"(r[0]), "=r"(r[1]) : "r"(addr));
}
// D += A(16x8) * B(8x8), tf32, fp32 accum.
__device__ __forceinline__ void mma8(float* c, const uint32_t* a, const uint32_t* b) {
    asm volatile(
        "mma.sync.aligned.m16n8k8.row.col.f32.tf32.tf32.f32 "
        "{%0,%1,%2,%3}, {%4,%5,%6,%7}, {%8,%9}, {%0,%1,%2,%3};"
        : "+f"(c[0]), "+f"(c[1]), "+f"(c[2]), "+f"(c[3])
        : "r"(a[0]), "r"(a[1]), "r"(a[2]), "r"(a[3]), "r"(b[0]), "r"(b[1]));
}

// ---------------- tf32 GEMM: C = A[M,K] @ W[K,N] -----------------------------
// 128 thr (4 warps, 2x2), tile 128x128x16, warp tile 64x64, double-buffered.
#define AP 20    // A pitch (ldmatrix rows 5 f4 apart: conflict-free)
#define WPX 136  // W pitch (b-frag LDS banks 8t+g: conflict-free)

__device__ __forceinline__ void tgemm_body(const float* __restrict__ A,
                                           const float* __restrict__ W,
                                           float* __restrict__ C,
                                           int M, int N, int K,
                                           uint32_t (*As)[128 * AP],
                                           uint32_t (*Ws)[16 * WPX]) {
    const int tid = threadIdx.x, wid = tid >> 5, lane = tid & 31;
    const int g = lane >> 2, tg = lane & 3;
    const int bm = blockIdx.y, bn = blockIdx.x;
    const int wm = wid >> 1, wn = wid & 1;
    const int arow_l = (lane & 7) + ((lane >> 3) & 1) * 8;  // ldmatrix row-in-16
    const int kcol_l = (lane >> 4) * 4;                     // ldmatrix k-half

    const uint32_t as_b = smem_u32(As);
    const uint32_t ws_b = smem_u32(Ws);

    // loader mapping
    const int row_a = tid >> 2, ca = (tid & 3) * 4;   // A: +r*32 rows
    const int kw = tid >> 5, nw = (tid & 31) * 4;     // W: +r*4 k-rows
    const float* Ap = A + (size_t)(bm * 128 + row_a) * K + ca;
    const float* Wp = W + (size_t)kw * N + bn * 128 + nw;

    float acc[4][8][4];
#pragma unroll
    for (int i = 0; i < 4; i++)
#pragma unroll
        for (int j = 0; j < 8; j++)
#pragma unroll
            for (int r = 0; r < 4; r++) acc[i][j][r] = 0.f;

    const int nk = K / 16;

    // preload tile 0
#pragma unroll
    for (int r = 0; r < 4; r++) {
        float4 av = *(const float4*)(Ap + (size_t)r * 32 * K);
        float4 wv = *(const float4*)(Wp + (size_t)r * 4 * N);
        *(uint4*)&As[0][(r * 32 + row_a) * AP + ca] =
            make_uint4(f2tf(av.x), f2tf(av.y), f2tf(av.z), f2tf(av.w));
        *(uint4*)&Ws[0][(r * 4 + kw) * WPX + nw] =
            make_uint4(f2tf(wv.x), f2tf(wv.y), f2tf(wv.z), f2tf(wv.w));
    }
    __syncthreads();

    for (int kt = 0; kt < nk; kt++) {
        const int buf = kt & 1;
        const bool more = (kt + 1) < nk;
        float4 av[4], wv[4];
        if (more) {
#pragma unroll
            for (int r = 0; r < 4; r++) {
                av[r] = *(const float4*)(Ap + (kt + 1) * 16 + (size_t)r * 32 * K);
                wv[r] = *(const float4*)(Wp + (size_t)((kt + 1) * 16 + r * 4) * N);
            }
        }

#pragma unroll
        for (int ks = 0; ks < 2; ks++) {
            const int k0 = ks * 8;
            uint32_t a[4][4];
#pragma unroll
            for (int mt = 0; mt < 4; mt++)
                ldmx4(a[mt], as_b + (uint32_t)(buf * 128 * AP +
                        (wm * 64 + mt * 16 + arow_l) * AP + k0 + kcol_l) * 4);
#pragma unroll
            for (int nt = 0; nt < 8; nt++) {
                uint32_t b[2];
                int cn = wn * 64 + nt * 8 + g;
                b[0] = Ws[buf][(k0 + tg) * WPX + cn];
                b[1] = Ws[buf][(k0 + tg + 4) * WPX + cn];
                mma8(acc[0][nt], a[0], b);
                mma8(acc[1][nt], a[1], b);
                mma8(acc[2][nt], a[2], b);
                mma8(acc[3][nt], a[3], b);
            }
        }

        if (more) {
            const int nb = buf ^ 1;
#pragma unroll
            for (int r = 0; r < 4; r++) {
                *(uint4*)&As[nb][(r * 32 + row_a) * AP + ca] =
                    make_uint4(f2tf(av[r].x), f2tf(av[r].y), f2tf(av[r].z), f2tf(av[r].w));
                *(uint4*)&Ws[nb][(r * 4 + kw) * WPX + nw] =
                    make_uint4(f2tf(wv[r].x), f2tf(wv[r].y), f2tf(wv[r].z), f2tf(wv[r].w));
            }
        }
        __syncthreads();
    }

#pragma unroll
    for (int mt = 0; mt < 4; mt++)
#pragma unroll
        for (int nt = 0; nt < 8; nt++) {
            int row = bm * 128 + wm * 64 + mt * 16 + g;
            int col = bn * 128 + wn * 64 + nt * 8 + 2 * tg;
            *(float2*)(C + (size_t)row * N + col) = make_float2(acc[mt][nt][0], acc[mt][nt][1]);
            *(float2*)(C + (size_t)(row + 8) * N + col) = make_float2(acc[mt][nt][2], acc[mt][nt][3]);
        }
}

__global__ __launch_bounds__(128) void tgemm(const float* __restrict__ A,
                                             const float* __restrict__ W,
                                             float* __restrict__ C,
                                             int M, int N, int K) {
    __shared__ uint32_t As[2][128 * AP];
    __shared__ uint32_t Ws[2][16 * WPX];
    tgemm_body(A, W, C, M, N, K, As, Ws);
}

__global__ __launch_bounds__(128) void tgemm_dual(const float* __restrict__ A,
                                                  const float* __restrict__ W0,
                                                  const float* __restrict__ W1,
                                                  float* __restrict__ C0,
                                                  float* __restrict__ C1,
                                                  int M, int N, int K) {
    __shared__ uint32_t As[2][128 * AP];
    __shared__ uint32_t Ws[2][16 * WPX];
    const float* W = blockIdx.z ? W1 : W0;
    float* C = blockIdx.z ? C1 : C0;
    tgemm_body(A, W, C, M, N, K, As, Ws);
}

// ---------------- Flash attention, tf32 mma, Q in registers ------------------
// Block 128 thr (4 warps); q-tile 128 (32 rows/warp); kv chunks of 64.
// P region doubles as Q staging (warp reads only its own rows before overwrite).
#define QP 68
#define VP 72
#define SM_P 0
#define SM_K (128 * QP)
#define SM_V (SM_K + 64 * QP)
#define SM_TOT (SM_V + 64 * VP)        // 17664 words = 70656 B

__global__ __launch_bounds__(128) void attn_mma() {
    extern __shared__ uint32_t sm4[];
    const uint32_t smb = smem_u32(sm4);
    uint32_t* Ks = sm4 + SM_K;
    uint32_t* Vs = sm4 + SM_V;
    uint32_t* Ps = sm4 + SM_P;

    const int qb = blockIdx.x, h = blockIdx.y, b = blockIdx.z;
    const int kvh = h >> 2;
    const int tid = threadIdx.x, w = tid >> 5, lane = tid & 31;
    const int g = lane >> 2, tg = lane & 3;
    const int arow_l = (lane & 7) + ((lane >> 3) & 1) * 8;
    const int kcol_l = (lane >> 4) * 4;
    const int brow_l = lane & 7, bk_l = ((lane >> 3) & 1) * 4;

    const float LOG2E = 1.4426950408889634f;
    const float sc2 = 0.125f * LOG2E;
    const float slope2 = ex2(-0.5f * (float)(h + 1)) * LOG2E;

    // stage Q tile [128 x 64] into P region
    {
        const float* qbase = g_q + (size_t)(b * NS + qb * 128) * ND + h * NHD;
#pragma unroll
        for (int rep = 0; rep < 16; rep++) {
            int idx = rep * 128 + tid;
            int r = idx >> 4, cg = (idx & 15) * 4;
            float4 v = *(const float4*)(qbase + (size_t)r * ND + cg);
            *(uint4*)&Ps[r * QP + cg] = make_uint4(f2tf(v.x), f2tf(v.y), f2tf(v.z), f2tf(v.w));
        }
    }
    __syncthreads();

    // Q fragments -> registers (warp-private rows)
    uint32_t qf[8][2][4];
#pragma unroll
    for (int ks = 0; ks < 8; ks++)
#pragma unroll
        for (int mt = 0; mt < 2; mt++)
            ldmx4(qf[ks][mt], smb + (uint32_t)(SM_P +
                    (w * 32 + mt * 16 + arow_l) * QP + ks * 8 + kcol_l) * 4);

    float m[4], l[4], O[2][8][4];
#pragma unroll
    for (int i = 0; i < 4; i++) { m[i] = -INFINITY; l[i] = 0.f; }
#pragma unroll
    for (int mt = 0; mt < 2; mt++)
#pragma unroll
        for (int nt = 0; nt < 8; nt++)
#pragma unroll
            for (int r = 0; r < 4; r++) O[mt][nt][r] = 0.f;

    float rowi[4];
#pragma unroll
    for (int mt = 0; mt < 2; mt++) {
        rowi[2 * mt]     = (float)(qb * 128 + w * 32 + mt * 16 + g);
        rowi[2 * mt + 1] = rowi[2 * mt] + 8.f;
    }

    for (int kt = 0; kt < NS / 64; kt++) {
        __syncthreads();
        const float* kbase = g_k + (size_t)(b * NS + kt * 64) * (NKV * NHD) + kvh * NHD;
        const float* vbase = g_v + (size_t)(b * NS + kt * 64) * (NKV * NHD) + kvh * NHD;
#pragma unroll
        for (int rep = 0; rep < 8; rep++) {
            int idx = rep * 128 + tid;
            int r = idx >> 4, cg = (idx & 15) * 4;
            float4 kv = *(const float4*)(kbase + (size_t)r * (NKV * NHD) + cg);
            *(uint4*)&Ks[r * QP + cg] = make_uint4(f2tf(kv.x), f2tf(kv.y), f2tf(kv.z), f2tf(kv.w));
            float4 vv = *(const float4*)(vbase + (size_t)r * (NKV * NHD) + cg);
            *(uint4*)&Vs[r * VP + cg] = make_uint4(f2tf(vv.x), f2tf(vv.y), f2tf(vv.z), f2tf(vv.w));
        }
        __syncthreads();

        // per-mt: S = Q K^T, softmax, P write
#pragma unroll
        for (int mt = 0; mt < 2; mt++) {
            float S[8][4];
#pragma unroll
            for (int nt = 0; nt < 8; nt++)
#pragma unroll
                for (int r = 0; r < 4; r++) S[nt][r] = 0.f;

#pragma unroll
            for (int ks = 0; ks < 8; ks++) {
#pragma unroll
                for (int nt = 0; nt < 8; nt++) {
                    uint32_t bb[2];
                    ldmx2(bb, smb + (uint32_t)(SM_K +
                            (nt * 8 + brow_l) * QP + ks * 8 + bk_l) * 4);
                    mma8(S[nt], qf[ks][mt], bb);
                }
            }

            float mx0 = -INFINITY, mx1 = -INFINITY;
#pragma unroll
            for (int nt = 0; nt < 8; nt++) {
                float j0 = (float)(kt * 64 + nt * 8 + 2 * tg);
                S[nt][0] = S[nt][0] * sc2 + slope2 * (j0 - rowi[2 * mt]);
                S[nt][1] = S[nt][1] * sc2 + slope2 * (j0 + 1.f - rowi[2 * mt]);
                S[nt][2] = S[nt][2] * sc2 + slope2 * (j0 - rowi[2 * mt + 1]);
                S[nt][3] = S[nt][3] * sc2 + slope2 * (j0 + 1.f - rowi[2 * mt + 1]);
                mx0 = fmaxf(mx0, fmaxf(S[nt][0], S[nt][1]));
                mx1 = fmaxf(mx1, fmaxf(S[nt][2], S[nt][3]));
            }
            mx0 = fmaxf(mx0, __shfl_xor_sync(0xffffffffu, mx0, 1));
            mx0 = fmaxf(mx0, __shfl_xor_sync(0xffffffffu, mx0, 2));
            mx1 = fmaxf(mx1, __shfl_xor_sync(0xffffffffu, mx1, 1));
            mx1 = fmaxf(mx1, __shfl_xor_sync(0xffffffffu, mx1, 2));

            float mn0 = fmaxf(m[2 * mt], mx0), mn1 = fmaxf(m[2 * mt + 1], mx1);
            float f0 = ex2(m[2 * mt] - mn0), f1 = ex2(m[2 * mt + 1] - mn1);
            m[2 * mt] = mn0; m[2 * mt + 1] = mn1;

            float rs0 = 0.f, rs1 = 0.f;
#pragma unroll
            for (int nt = 0; nt < 8; nt++) {
                S[nt][0] = ex2(S[nt][0] - mn0);
                S[nt][1] = ex2(S[nt][1] - mn0);
                S[nt][2] = ex2(S[nt][2] - mn1);
                S[nt][3] = ex2(S[nt][3] - mn1);
                rs0 += S[nt][0] + S[nt][1];
                rs1 += S[nt][2] + S[nt][3];
            }
            rs0 += __shfl_xor_sync(0xffffffffu, rs0, 1);
            rs0 += __shfl_xor_sync(0xffffffffu, rs0, 2);
            rs1 += __shfl_xor_sync(0xffffffffu, rs1, 1);
            rs1 += __shfl_xor_sync(0xffffffffu, rs1, 2);
            l[2 * mt] = l[2 * mt] * f0 + rs0;
            l[2 * mt + 1] = l[2 * mt + 1] * f1 + rs1;

#pragma unroll
            for (int nt = 0; nt < 8; nt++) {
                O[mt][nt][0] *= f0; O[mt][nt][1] *= f0;
                O[mt][nt][2] *= f1; O[mt][nt][3] *= f1;
            }

            // P write (tf32) to warp-private rows
            int rL = w * 32 + mt * 16 + g, rH = rL + 8;
#pragma unroll
            for (int nt = 0; nt < 8; nt++) {
                *(uint2*)&Ps[rL * QP + nt * 8 + 2 * tg] =
                    make_uint2(f2tf(S[nt][0]), f2tf(S[nt][1]));
                *(uint2*)&Ps[rH * QP + nt * 8 + 2 * tg] =
                    make_uint2(f2tf(S[nt][2]), f2tf(S[nt][3]));
            }
        }
        __syncwarp();

        // O += P @ V
#pragma unroll
        for (int ks = 0; ks < 8; ks++) {
            const int k0 = ks * 8;
            uint32_t a[2][4];
#pragma unroll
            for (int mt = 0; mt < 2; mt++)
                ldmx4(a[mt], smb + (uint32_t)(SM_P +
                        (w * 32 + mt * 16 + arow_l) * QP + k0 + kcol_l) * 4);
#pragma unroll
            for (int nt = 0; nt < 8; nt++) {
                uint32_t bb[2];
                bb[0] = Vs[(k0 + tg) * VP + nt * 8 + g];
                bb[1] = Vs[(k0 + tg + 4) * VP + nt * 8 + g];
                mma8(O[0][nt], a[0], bb);
                mma8(O[1][nt], a[1], bb);
            }
        }
        __syncwarp();
    }

    // epilogue
#pragma unroll
    for (int mt = 0; mt < 2; mt++) {
        float inv0 = 1.f / l[2 * mt], inv1 = 1.f / l[2 * mt + 1];
        int rL = qb * 128 + w * 32 + mt * 16 + g;
        float* ob = g_o + (size_t)(b * NS + rL) * ND + h * NHD;
#pragma unroll
        for (int nt = 0; nt < 8; nt++) {
            *(float2*)(ob + nt * 8 + 2 * tg) =
                make_float2(O[mt][nt][0] * inv0, O[mt][nt][1] * inv0);
            *(float2*)(ob + (size_t)8 * ND + nt * 8 + 2 * tg) =
                make_float2(O[mt][nt][2] * inv1, O[mt][nt][3] * inv1);
        }
    }
}

// ---------------- launch ------------------------------------------------------
extern "C" void kernel_launch(void* const* d_in, const int* in_sizes, int n_in,
                              void* d_out, int out_size) {
    const float* x  = (const float*)d_in[0];
    const float* Wq = (const float*)d_in[1];
    const float* Wk = (const float*)d_in[2];
    const float* Wv = (const float*)d_in[3];
    const float* Wo = (const float*)d_in[4];
    float* out = (float*)d_out;

    float *q, *k, *v, *o;
    cudaGetSymbolAddress((void**)&q, g_q);
    cudaGetSymbolAddress((void**)&k, g_k);
    cudaGetSymbolAddress((void**)&v, g_v);
    cudaGetSymbolAddress((void**)&o, g_o);

    const int smem_attn = SM_TOT * sizeof(uint32_t);   // 70656 B
    cudaFuncSetAttribute(attn_mma, cudaFuncAttributeMaxDynamicSharedMemorySize, smem_attn);

    tgemm<<<dim3(ND / 128, MTOT / 128), 128>>>(x, Wq, q, MTOT, ND, ND);
    tgemm_dual<<<dim3(256 / 128, MTOT / 128, 2), 128>>>(x, Wk, Wv, k, v, MTOT, 256, ND);

    attn_mma<<<dim3(NS / 128, NH, NB), 128, smem_attn>>>();

    tgemm<<<dim3(ND / 128, MTOT / 128), 128>>>(o, Wo, out, MTOT, ND, ND);
}